// round 1
// baseline (speedup 1.0000x reference)
#include <cuda_runtime.h>
#include <math.h>
#include <float.h>

#define IMG_H 128
#define IMG_W 128
#define MAXN  4096
#define SORTN 4096

// ---------------- device scratch (no allocations allowed) ----------------
__device__ float g_depth[MAXN];
__device__ float g_mx[MAXN], g_my[MAXN];
__device__ float g_A[MAXN],  g_B[MAXN],  g_C[MAXN];
__device__ float g_op[MAXN], g_r[MAXN];
__device__ float g_cr[MAXN], g_cg[MAXN], g_cb[MAXN];
// depth-sorted copies
__device__ float sr_mx[MAXN], sr_my[MAXN], sr_A[MAXN], sr_B[MAXN], sr_C[MAXN];
__device__ float sr_op[MAXN], sr_r[MAXN], sr_cr[MAXN], sr_cg[MAXN], sr_cb[MAXN];

// ---------------- kernel 1: per-gaussian preprocess ----------------
__global__ void preprocess_kernel(
    const float* __restrict__ means, const float* __restrict__ sh,
    const float* __restrict__ opac,  const float* __restrict__ scales,
    const float* __restrict__ rots,  const float* __restrict__ cam_pos,
    const float* __restrict__ cam_rot, const float* __restrict__ thf_p,
    const float* __restrict__ near_far, int n)
{
    int g = blockIdx.x * blockDim.x + threadIdx.x;
    if (g >= n) return;

    float thf = thf_p[0];
    float fx = (float)IMG_W / (2.0f * thf);
    float fy = (float)IMG_H / (2.0f * thf);

    float rx = means[3*g+0] - cam_pos[0];
    float ry = means[3*g+1] - cam_pos[1];
    float rz = means[3*g+2] - cam_pos[2];

    float W0=cam_rot[0],W1=cam_rot[1],W2=cam_rot[2];
    float W3=cam_rot[3],W4=cam_rot[4],W5=cam_rot[5];
    float W6=cam_rot[6],W7=cam_rot[7],W8=cam_rot[8];

    float t0 = W0*rx + W1*ry + W2*rz;
    float t1 = W3*rx + W4*ry + W5*rz;
    float tz = W6*rx + W7*ry + W8*rz;

    float lim = 1.3f * thf;
    float txz = t0 / tz, tyz = t1 / tz;
    float txc = fminf(fmaxf(txz, -lim), lim) * tz;
    float tyc = fminf(fmaxf(tyz, -lim), lim) * tz;

    // quaternion -> rotation
    float qr = rots[4*g+0], qx = rots[4*g+1], qy = rots[4*g+2], qz = rots[4*g+3];
    float qn = 1.0f / sqrtf(qr*qr + qx*qx + qy*qy + qz*qz);
    qr*=qn; qx*=qn; qy*=qn; qz*=qn;
    float R00 = 1.f - 2.f*(qy*qy + qz*qz), R01 = 2.f*(qx*qy - qr*qz), R02 = 2.f*(qx*qz + qr*qy);
    float R10 = 2.f*(qx*qy + qr*qz), R11 = 1.f - 2.f*(qx*qx + qz*qz), R12 = 2.f*(qy*qz - qr*qx);
    float R20 = 2.f*(qx*qz - qr*qy), R21 = 2.f*(qy*qz + qr*qx), R22 = 1.f - 2.f*(qx*qx + qy*qy);

    float s0 = scales[3*g+0], s1 = scales[3*g+1], s2 = scales[3*g+2];
    float M00=R00*s0, M01=R01*s1, M02=R02*s2;
    float M10=R10*s0, M11=R11*s1, M12=R12*s2;
    float M20=R20*s0, M21=R21*s1, M22=R22*s2;

    // cov3 = M M^T (symmetric)
    float c00 = M00*M00 + M01*M01 + M02*M02;
    float c01 = M00*M10 + M01*M11 + M02*M12;
    float c02 = M00*M20 + M01*M21 + M02*M22;
    float c11 = M10*M10 + M11*M11 + M12*M12;
    float c12 = M10*M20 + M11*M21 + M12*M22;
    float c22 = M20*M20 + M21*M21 + M22*M22;

    float z2 = tz * tz;
    float J00 = fx / tz, J02 = -fx * txc / z2;
    float J11 = fy / tz, J12 = -fy * tyc / z2;

    // T2 = J * cam_rot  (2x3)
    float T00 = J00*W0 + J02*W6, T01 = J00*W1 + J02*W7, T02 = J00*W2 + J02*W8;
    float T10 = J11*W3 + J12*W6, T11 = J11*W4 + J12*W7, T12 = J11*W5 + J12*W8;

    // V = T2 * cov3 (2x3), cov2 = V * T2^T
    float V00 = T00*c00 + T01*c01 + T02*c02;
    float V01 = T00*c01 + T01*c11 + T02*c12;
    float V02 = T00*c02 + T01*c12 + T02*c22;
    float V10 = T10*c00 + T11*c01 + T12*c02;
    float V11 = T10*c01 + T11*c11 + T12*c12;
    float V12 = T10*c02 + T11*c12 + T12*c22;

    float cov00 = V00*T00 + V01*T01 + V02*T02;
    float cov01 = V00*T10 + V01*T11 + V02*T12;
    float cov11 = V10*T10 + V11*T11 + V12*T12;

    float a = cov00 + 0.3f, c = cov11 + 0.3f, b = cov01;
    float det = a*c - b*b;
    bool valid = (tz > near_far[0]) && (tz < near_far[1]) && (det > 0.0f);

    float invDet = 1.0f / det;
    float A =  c * invDet;
    float B = -b * invDet;
    float C =  a * invDet;

    float mx = fx * txz + ((float)IMG_W - 1.0f) * 0.5f;
    float my = fy * tyz + ((float)IMG_H - 1.0f) * 0.5f;

    // SH color
    float dn = 1.0f / sqrtf(rx*rx + ry*ry + rz*rz);
    float dx = rx*dn, dy = ry*dn, dz = rz*dn;
    float xx = dx*dx, yy = dy*dy, zz = dz*dz;
    float xy = dx*dy, yz = dy*dz, xz = dx*dz;

    float bas[16];
    bas[0]  =  0.28209479177387814f;
    bas[1]  = -0.4886025119029199f * dy;
    bas[2]  =  0.4886025119029199f * dz;
    bas[3]  = -0.4886025119029199f * dx;
    bas[4]  =  1.0925484305920792f * xy;
    bas[5]  = -1.0925484305920792f * yz;
    bas[6]  =  0.31539156525252005f * (2.0f*zz - xx - yy);
    bas[7]  = -1.0925484305920792f * xz;
    bas[8]  =  0.5462742152960396f * (xx - yy);
    bas[9]  = -0.5900435899266435f * dy * (3.0f*xx - yy);
    bas[10] =  2.890611442640554f  * xy * dz;
    bas[11] = -0.4570457994644658f * dy * (4.0f*zz - xx - yy);
    bas[12] =  0.3731763325901154f * dz * (2.0f*zz - 3.0f*xx - 3.0f*yy);
    bas[13] = -0.4570457994644658f * dx * (4.0f*zz - xx - yy);
    bas[14] =  1.445305721320277f  * dz * (xx - yy);
    bas[15] = -0.5900435899266435f * dx * (xx - 3.0f*yy);

    const float* shg = sh + (size_t)g * 48;
    float col[3];
    #pragma unroll
    for (int ch = 0; ch < 3; ch++) {
        float r = 0.0f;
        #pragma unroll
        for (int k = 0; k < 16; k++) r += bas[k] * shg[k*3 + ch];
        col[ch] = fmaxf(r + 0.5f, 0.0f);
    }

    float o = opac[g];

    // conservative cull radius via min-eigenvalue bound of conic Q=[[A,B],[B,C]]
    float rad;
    if (!valid) {
        rad = -1.0f;
    } else {
        float thr = logf(255.0f * o);         // alpha(d) <= o*exp(-0.5*lamMin*d^2)
        if (thr <= 0.0f) {
            rad = -1.0f;                      // never reaches 1/255
        } else {
            float disc = sqrtf(fmaxf((A - C)*(A - C) + 4.0f*B*B, 0.0f));
            float lamMin = 0.5f * ((A + C) - disc);
            if (lamMin < 1e-12f) rad = 1e9f;  // no cull (defensive)
            else rad = sqrtf(2.0f * thr / lamMin) * 1.01f + 2.0f; // fp margin
        }
    }

    g_depth[g] = tz;
    g_mx[g] = mx;  g_my[g] = my;
    g_A[g] = A;    g_B[g] = B;    g_C[g] = C;
    g_op[g] = o;   g_r[g] = rad;
    g_cr[g] = col[0]; g_cg[g] = col[1]; g_cb[g] = col[2];
}

// ---------------- kernel 2: bitonic depth sort + gather ----------------
__global__ void sort_gather_kernel(int n)
{
    __shared__ float key[SORTN];
    __shared__ int   val[SORTN];
    int tid = threadIdx.x;

    for (int i = tid; i < SORTN; i += 1024) {
        key[i] = (i < n) ? g_depth[i] : FLT_MAX;
        val[i] = i;
    }
    __syncthreads();

    for (int size = 2; size <= SORTN; size <<= 1) {
        for (int stride = size >> 1; stride > 0; stride >>= 1) {
            for (int i = tid; i < SORTN/2; i += 1024) {
                int a = ((i & ~(stride - 1)) << 1) | (i & (stride - 1));
                int b = a + stride;
                bool up = ((a & size) == 0);
                float ka = key[a], kb = key[b];
                int   va = val[a], vb = val[b];
                // (key, idx) lexicographic => stable for distinct keys
                bool gt = (ka > kb) || (ka == kb && va > vb);
                if (gt == up) {
                    key[a] = kb; key[b] = ka;
                    val[a] = vb; val[b] = va;
                }
            }
            __syncthreads();
        }
    }

    for (int i = tid; i < n; i += 1024) {
        int o = val[i];
        sr_mx[i] = g_mx[o]; sr_my[i] = g_my[o];
        sr_A[i]  = g_A[o];  sr_B[i]  = g_B[o];  sr_C[i] = g_C[o];
        sr_op[i] = g_op[o]; sr_r[i]  = g_r[o];
        sr_cr[i] = g_cr[o]; sr_cg[i] = g_cg[o]; sr_cb[i] = g_cb[o];
    }
}

// ---------------- kernel 3: tiled rasterize (16x16 tiles) ----------------
__global__ void __launch_bounds__(256)
rasterize_kernel(const float* __restrict__ bg, int n, float* __restrict__ out)
{
    const int tileX = blockIdx.x & 7;
    const int tileY = blockIdx.x >> 3;
    const int tid = threadIdx.x;
    const int lx = tid & 15, ly = tid >> 4;
    const int pxI = tileX * 16 + lx;
    const int pyI = tileY * 16 + ly;
    const float pxf = (float)pxI, pyf = (float)pyI;

    const float tx0 = (float)(tileX * 16);
    const float tx1 = (float)(tileX * 16 + 15);
    const float ty0 = (float)(tileY * 16);
    const float ty1 = (float)(tileY * 16 + 15);

    __shared__ float h_mx[256], h_my[256], h_A[256], h_B[256], h_C[256];
    __shared__ float h_op[256], h_cr[256], h_cg[256], h_cb[256];
    __shared__ int wc[8];
    __shared__ int warpOff[9];

    float T = 1.0f, accR = 0.0f, accG = 0.0f, accB = 0.0f;

    const int lane = tid & 31, warp = tid >> 5;
    const unsigned laneMaskLt = (1u << lane) - 1u;

    for (int c0 = 0; c0 < n; c0 += 256) {
        int g = c0 + tid;
        bool pass = false;
        float mx = 0.f, my = 0.f;
        if (g < n) {
            mx = sr_mx[g]; my = sr_my[g];
            float r = sr_r[g];
            pass = (r > 0.0f) &&
                   (mx + r >= tx0) && (mx - r <= tx1) &&
                   (my + r >= ty0) && (my - r <= ty1);
        }
        unsigned bal = __ballot_sync(0xffffffffu, pass);
        int pfx = __popc(bal & laneMaskLt);
        if (lane == 0) wc[warp] = __popc(bal);
        __syncthreads();
        if (tid == 0) {
            int s = 0;
            #pragma unroll
            for (int w = 0; w < 8; w++) { warpOff[w] = s; s += wc[w]; }
            warpOff[8] = s;
        }
        __syncthreads();
        if (pass) {
            int p = warpOff[warp] + pfx;
            h_mx[p] = mx;       h_my[p] = my;
            h_A[p]  = sr_A[g];  h_B[p]  = sr_B[g];  h_C[p] = sr_C[g];
            h_op[p] = sr_op[g];
            h_cr[p] = sr_cr[g]; h_cg[p] = sr_cg[g]; h_cb[p] = sr_cb[g];
        }
        __syncthreads();
        int tot = warpOff[8];

        for (int j = 0; j < tot; j++) {
            float ddx = pxf - h_mx[j];
            float ddy = pyf - h_my[j];
            float power = -0.5f * (h_A[j]*ddx*ddx + h_C[j]*ddy*ddy) - h_B[j]*ddx*ddy;
            if (power <= 0.0f) {
                float alpha = fminf(h_op[j] * expf(power), 0.99f);
                if (alpha >= 0.00392156862745098f) {
                    float w = alpha * T;
                    accR += w * h_cr[j];
                    accG += w * h_cg[j];
                    accB += w * h_cb[j];
                    T *= (1.0f - alpha);
                }
            }
        }
        __syncthreads();
    }

    const int pix = pyI * IMG_W + pxI;
    out[0 * IMG_H * IMG_W + pix] = accR + T * bg[0];
    out[1 * IMG_H * IMG_W + pix] = accG + T * bg[1];
    out[2 * IMG_H * IMG_W + pix] = accB + T * bg[2];
}

// ---------------- launch ----------------
extern "C" void kernel_launch(void* const* d_in, const int* in_sizes, int n_in,
                              void* d_out, int out_size)
{
    const float* means    = (const float*)d_in[0];
    const float* sh       = (const float*)d_in[1];
    const float* opac     = (const float*)d_in[2];
    const float* scales   = (const float*)d_in[3];
    const float* rots     = (const float*)d_in[4];
    const float* cam_pos  = (const float*)d_in[5];
    const float* cam_rot  = (const float*)d_in[6];
    const float* thf      = (const float*)d_in[7];
    const float* bg       = (const float*)d_in[8];
    const float* near_far = (const float*)d_in[9];

    int n = in_sizes[0] / 3;
    if (n > MAXN) n = MAXN;

    preprocess_kernel<<<(n + 127) / 128, 128>>>(means, sh, opac, scales, rots,
                                                cam_pos, cam_rot, thf, near_far, n);
    sort_gather_kernel<<<1, 1024>>>(n);
    rasterize_kernel<<<64, 256>>>(bg, n, (float*)d_out);
}

// round 2
// speedup vs baseline: 1.9965x; 1.9965x over previous
#include <cuda_runtime.h>
#include <math.h>
#include <float.h>

#define IMG_H 128
#define IMG_W 128
#define MAXN  2048

// ---------------- device scratch (no allocations allowed) ----------------
__device__ float  g_depth[MAXN];
__device__ float4 g_p1[MAXN];   // mx, my, A, B
__device__ float4 g_p2[MAXN];   // C, op, cr, cg
__device__ float  g_cb[MAXN];
__device__ float  g_r[MAXN];
// depth-sorted copies
__device__ float4 sr_p1[MAXN];
__device__ float4 sr_p2[MAXN];
__device__ float  sr_cb[MAXN];
__device__ float  sr_r[MAXN];

// ---------------- kernel 1: per-gaussian preprocess ----------------
__global__ void preprocess_kernel(
    const float* __restrict__ means, const float* __restrict__ sh,
    const float* __restrict__ opac,  const float* __restrict__ scales,
    const float* __restrict__ rots,  const float* __restrict__ cam_pos,
    const float* __restrict__ cam_rot, const float* __restrict__ thf_p,
    const float* __restrict__ near_far, int n)
{
    int g = blockIdx.x * blockDim.x + threadIdx.x;
    if (g >= n) return;

    float thf = thf_p[0];
    float fx = (float)IMG_W / (2.0f * thf);
    float fy = (float)IMG_H / (2.0f * thf);

    float rx = means[3*g+0] - cam_pos[0];
    float ry = means[3*g+1] - cam_pos[1];
    float rz = means[3*g+2] - cam_pos[2];

    float W0=cam_rot[0],W1=cam_rot[1],W2=cam_rot[2];
    float W3=cam_rot[3],W4=cam_rot[4],W5=cam_rot[5];
    float W6=cam_rot[6],W7=cam_rot[7],W8=cam_rot[8];

    float t0 = W0*rx + W1*ry + W2*rz;
    float t1 = W3*rx + W4*ry + W5*rz;
    float tz = W6*rx + W7*ry + W8*rz;

    float lim = 1.3f * thf;
    float txz = t0 / tz, tyz = t1 / tz;
    float txc = fminf(fmaxf(txz, -lim), lim) * tz;
    float tyc = fminf(fmaxf(tyz, -lim), lim) * tz;

    // quaternion -> rotation
    float qr = rots[4*g+0], qx = rots[4*g+1], qy = rots[4*g+2], qz = rots[4*g+3];
    float qn = 1.0f / sqrtf(qr*qr + qx*qx + qy*qy + qz*qz);
    qr*=qn; qx*=qn; qy*=qn; qz*=qn;
    float R00 = 1.f - 2.f*(qy*qy + qz*qz), R01 = 2.f*(qx*qy - qr*qz), R02 = 2.f*(qx*qz + qr*qy);
    float R10 = 2.f*(qx*qy + qr*qz), R11 = 1.f - 2.f*(qx*qx + qz*qz), R12 = 2.f*(qy*qz - qr*qx);
    float R20 = 2.f*(qx*qz - qr*qy), R21 = 2.f*(qy*qz + qr*qx), R22 = 1.f - 2.f*(qx*qx + qy*qy);

    float s0 = scales[3*g+0], s1 = scales[3*g+1], s2 = scales[3*g+2];
    float M00=R00*s0, M01=R01*s1, M02=R02*s2;
    float M10=R10*s0, M11=R11*s1, M12=R12*s2;
    float M20=R20*s0, M21=R21*s1, M22=R22*s2;

    // cov3 = M M^T (symmetric)
    float c00 = M00*M00 + M01*M01 + M02*M02;
    float c01 = M00*M10 + M01*M11 + M02*M12;
    float c02 = M00*M20 + M01*M21 + M02*M22;
    float c11 = M10*M10 + M11*M11 + M12*M12;
    float c12 = M10*M20 + M11*M21 + M12*M22;
    float c22 = M20*M20 + M21*M21 + M22*M22;

    float z2 = tz * tz;
    float J00 = fx / tz, J02 = -fx * txc / z2;
    float J11 = fy / tz, J12 = -fy * tyc / z2;

    // T2 = J * cam_rot  (2x3)
    float T00 = J00*W0 + J02*W6, T01 = J00*W1 + J02*W7, T02 = J00*W2 + J02*W8;
    float T10 = J11*W3 + J12*W6, T11 = J11*W4 + J12*W7, T12 = J11*W5 + J12*W8;

    // V = T2 * cov3 (2x3), cov2 = V * T2^T
    float V00 = T00*c00 + T01*c01 + T02*c02;
    float V01 = T00*c01 + T01*c11 + T02*c12;
    float V02 = T00*c02 + T01*c12 + T02*c22;
    float V10 = T10*c00 + T11*c01 + T12*c02;
    float V11 = T10*c01 + T11*c11 + T12*c12;
    float V12 = T10*c02 + T11*c12 + T12*c22;

    float cov00 = V00*T00 + V01*T01 + V02*T02;
    float cov01 = V00*T10 + V01*T11 + V02*T12;
    float cov11 = V10*T10 + V11*T11 + V12*T12;

    float a = cov00 + 0.3f, c = cov11 + 0.3f, b = cov01;
    float det = a*c - b*b;
    bool valid = (tz > near_far[0]) && (tz < near_far[1]) && (det > 0.0f);

    float invDet = 1.0f / det;
    float A =  c * invDet;
    float B = -b * invDet;
    float C =  a * invDet;

    float mx = fx * txz + ((float)IMG_W - 1.0f) * 0.5f;
    float my = fy * tyz + ((float)IMG_H - 1.0f) * 0.5f;

    // SH color
    float dn = 1.0f / sqrtf(rx*rx + ry*ry + rz*rz);
    float dx = rx*dn, dy = ry*dn, dz = rz*dn;
    float xx = dx*dx, yy = dy*dy, zz = dz*dz;
    float xy = dx*dy, yz = dy*dz, xz = dx*dz;

    float bas[16];
    bas[0]  =  0.28209479177387814f;
    bas[1]  = -0.4886025119029199f * dy;
    bas[2]  =  0.4886025119029199f * dz;
    bas[3]  = -0.4886025119029199f * dx;
    bas[4]  =  1.0925484305920792f * xy;
    bas[5]  = -1.0925484305920792f * yz;
    bas[6]  =  0.31539156525252005f * (2.0f*zz - xx - yy);
    bas[7]  = -1.0925484305920792f * xz;
    bas[8]  =  0.5462742152960396f * (xx - yy);
    bas[9]  = -0.5900435899266435f * dy * (3.0f*xx - yy);
    bas[10] =  2.890611442640554f  * xy * dz;
    bas[11] = -0.4570457994644658f * dy * (4.0f*zz - xx - yy);
    bas[12] =  0.3731763325901154f * dz * (2.0f*zz - 3.0f*xx - 3.0f*yy);
    bas[13] = -0.4570457994644658f * dx * (4.0f*zz - xx - yy);
    bas[14] =  1.445305721320277f  * dz * (xx - yy);
    bas[15] = -0.5900435899266435f * dx * (xx - 3.0f*yy);

    const float* shg = sh + (size_t)g * 48;
    float col[3];
    #pragma unroll
    for (int ch = 0; ch < 3; ch++) {
        float r = 0.0f;
        #pragma unroll
        for (int k = 0; k < 16; k++) r += bas[k] * shg[k*3 + ch];
        col[ch] = fmaxf(r + 0.5f, 0.0f);
    }

    float o = opac[g];

    // conservative cull radius via min-eigenvalue bound of conic Q=[[A,B],[B,C]]
    float rad;
    if (!valid) {
        rad = -1.0f;
    } else {
        float thr = logf(255.0f * o);
        if (thr <= 0.0f) {
            rad = -1.0f;
        } else {
            float disc = sqrtf(fmaxf((A - C)*(A - C) + 4.0f*B*B, 0.0f));
            float lamMin = 0.5f * ((A + C) - disc);
            if (lamMin < 1e-12f) rad = 1e9f;
            else rad = sqrtf(2.0f * thr / lamMin) * 1.01f + 2.0f;
        }
    }

    g_depth[g] = tz;
    g_p1[g] = make_float4(mx, my, A, B);
    g_p2[g] = make_float4(C, o, col[0], col[1]);
    g_cb[g] = col[2];
    g_r[g]  = rad;
}

// ---------------- kernel 2: parallel rank sort + scatter ----------------
// rank[i] = #{ j : key[j] < key[i] || (key[j]==key[i] && j < i) }  == stable argsort slot
__global__ void __launch_bounds__(256)
rank_scatter_kernel(int n)
{
    __shared__ float keys[MAXN];
    int tid = threadIdx.x;
    for (int i = tid; i < n; i += 256) keys[i] = g_depth[i];
    __syncthreads();

    int g = blockIdx.x * 256 + tid;
    if (g >= n) return;

    float ki = keys[g];
    int rank = 0;
    #pragma unroll 8
    for (int j = 0; j < n; j++) {
        float kj = keys[j];
        rank += (kj < ki) || (kj == ki && j < g);
    }

    sr_p1[rank] = g_p1[g];
    sr_p2[rank] = g_p2[g];
    sr_cb[rank] = g_cb[g];
    sr_r[rank]  = g_r[g];
}

// ---------------- kernel 3: tiled rasterize (16x16 tiles) ----------------
__global__ void __launch_bounds__(256)
rasterize_kernel(const float* __restrict__ bg, int n, float* __restrict__ out)
{
    const int tileX = blockIdx.x & 7;
    const int tileY = blockIdx.x >> 3;
    const int tid = threadIdx.x;
    const int lx = tid & 15, ly = tid >> 4;
    const int pxI = tileX * 16 + lx;
    const int pyI = tileY * 16 + ly;
    const float pxf = (float)pxI, pyf = (float)pyI;

    const float tx0 = (float)(tileX * 16);
    const float tx1 = (float)(tileX * 16 + 15);
    const float ty0 = (float)(tileY * 16);
    const float ty1 = (float)(tileY * 16 + 15);

    __shared__ float4 sh1[256];        // mx,my,A,B
    __shared__ float4 sh2[256];        // C,op,cr,cg
    __shared__ float  shb[256];        // cb
    __shared__ int wc[8];
    __shared__ int warpOff[9];

    float T = 1.0f, accR = 0.0f, accG = 0.0f, accB = 0.0f;

    const int lane = tid & 31, warp = tid >> 5;
    const unsigned laneMaskLt = (1u << lane) - 1u;

    for (int c0 = 0; c0 < n; c0 += 256) {
        int g = c0 + tid;
        bool pass = false;
        float4 p1;
        if (g < n) {
            p1 = sr_p1[g];
            float r = sr_r[g];
            pass = (r > 0.0f) &&
                   (p1.x + r >= tx0) && (p1.x - r <= tx1) &&
                   (p1.y + r >= ty0) && (p1.y - r <= ty1);
        }
        unsigned bal = __ballot_sync(0xffffffffu, pass);
        int pfx = __popc(bal & laneMaskLt);
        if (lane == 0) wc[warp] = __popc(bal);
        __syncthreads();
        if (warp == 0) {
            int v = (lane < 8) ? wc[lane] : 0;
            int e = 0;
            #pragma unroll
            for (int s = 1; s < 8; s <<= 1) {
                int t = __shfl_up_sync(0xffffffffu, v, s);
                if (lane >= s) v += t;
            }
            e = v - ((lane < 8) ? wc[lane] : 0);
            if (lane < 8) warpOff[lane] = e;
            if (lane == 7) warpOff[8] = v;
        }
        __syncthreads();
        if (pass) {
            int p = warpOff[warp] + pfx;
            sh1[p] = p1;
            sh2[p] = sr_p2[g];
            shb[p] = sr_cb[g];
        }
        __syncthreads();
        int tot = warpOff[8];

        for (int j = 0; j < tot; j++) {
            float4 q1 = sh1[j];
            float4 q2 = sh2[j];
            float cb = shb[j];
            float ddx = pxf - q1.x;
            float ddy = pyf - q1.y;
            float power = -0.5f * (q1.z*ddx*ddx + q2.x*ddy*ddy) - q1.w*ddx*ddy;
            float alpha = fminf(q2.y * __expf(power), 0.99f);
            bool ok = (power <= 0.0f) && (alpha >= 0.00392156862745098f);
            alpha = ok ? alpha : 0.0f;
            float w = alpha * T;
            accR += w * q2.z;
            accG += w * q2.w;
            accB += w * cb;
            T *= (1.0f - alpha);
        }
        __syncthreads();
    }

    const int pix = pyI * IMG_W + pxI;
    out[0 * IMG_H * IMG_W + pix] = accR + T * bg[0];
    out[1 * IMG_H * IMG_W + pix] = accG + T * bg[1];
    out[2 * IMG_H * IMG_W + pix] = accB + T * bg[2];
}

// ---------------- launch ----------------
extern "C" void kernel_launch(void* const* d_in, const int* in_sizes, int n_in,
                              void* d_out, int out_size)
{
    const float* means    = (const float*)d_in[0];
    const float* sh       = (const float*)d_in[1];
    const float* opac     = (const float*)d_in[2];
    const float* scales   = (const float*)d_in[3];
    const float* rots     = (const float*)d_in[4];
    const float* cam_pos  = (const float*)d_in[5];
    const float* cam_rot  = (const float*)d_in[6];
    const float* thf      = (const float*)d_in[7];
    const float* bg       = (const float*)d_in[8];
    const float* near_far = (const float*)d_in[9];

    int n = in_sizes[0] / 3;
    if (n > MAXN) n = MAXN;

    preprocess_kernel<<<(n + 127) / 128, 128>>>(means, sh, opac, scales, rots,
                                                cam_pos, cam_rot, thf, near_far, n);
    rank_scatter_kernel<<<(n + 255) / 256, 256>>>(n);
    rasterize_kernel<<<64, 256>>>(bg, n, (float*)d_out);
}